// round 15
// baseline (speedup 1.0000x reference)
#include <cuda_runtime.h>
#include <cuda_bf16.h>

#define B_   8
#define C_   64
#define O_   64
#define H_   128
#define W_   128
#define HW_  16384
#define PAD_ 3
#define R_   49
#define HSTR 48                 // halo row stride (floats): conflict-free LDS.64/.128
#define CH_STRIDE (22 * HSTR)   // 1056 floats per halo channel
#define HALO_F (8 * CH_STRIDE)  // 8448 floats per halo buffer

// attn smem layout (floats): sH0 | sH1 | region(8192: sX0|sX1 / xch / pbuf)
#define SH0_OFF  0
#define SH1_OFF  HALO_F
#define PB_OFF   (2 * HALO_F)
#define SX0_OFF  PB_OFF
#define SX1_OFF  (PB_OFF + 2048)
#define ATTN_SMEM ((2 * HALO_F + 8192) * 4)   // 100352 B; 2 blocks/SM (RF-limited)

// qkv mma smem (bytes)
#define XHI_OFF  0
#define XLO_OFF  17408
#define WMH_OFF  34816
#define WML_OFF  44032
#define WWH_OFF  53248
#define WWL_OFF  62464
#define QKV_SMEM 71680
#define XROWB    272
#define WROWB    144
#define DSTR     132

// Scratch (device globals)
__device__ float g_y[B_ * C_ * HW_];
__device__ float g_v[B_ * C_ * HW_];
__device__ float g_M[64 * 64];

// -------------------- cp.async helpers --------------------
__device__ __forceinline__ void cpa4(float* smem_dst, const float* gsrc) {
    unsigned sa = (unsigned)__cvta_generic_to_shared(smem_dst);
    asm volatile("cp.async.ca.shared.global [%0], [%1], 4;" :: "r"(sa), "l"(gsrc));
}
__device__ __forceinline__ void cpa16(float* smem_dst, const float* gsrc) {
    unsigned sa = (unsigned)__cvta_generic_to_shared(smem_dst);
    asm volatile("cp.async.cg.shared.global [%0], [%1], 16;" :: "r"(sa), "l"(gsrc));
}
__device__ __forceinline__ void cpa_commit() {
    asm volatile("cp.async.commit_group;" ::: "memory");
}
template<int N>
__device__ __forceinline__ void cpa_wait() {
    asm volatile("cp.async.wait_group %0;" :: "n"(N) : "memory");
}

// -------------------- mma / ldmatrix helpers --------------------
__device__ __forceinline__ unsigned smem_u32(const void* p) {
    unsigned a;
    asm("{ .reg .u64 t; cvta.to.shared.u64 t, %1; cvt.u32.u64 %0, t; }"
        : "=r"(a) : "l"(p));
    return a;
}
__device__ __forceinline__ void ldsm4t(unsigned& r0, unsigned& r1,
                                       unsigned& r2, unsigned& r3, unsigned a) {
    asm volatile("ldmatrix.sync.aligned.m8n8.x4.trans.shared.b16 {%0,%1,%2,%3},[%4];"
                 : "=r"(r0), "=r"(r1), "=r"(r2), "=r"(r3) : "r"(a));
}
__device__ __forceinline__ void ldsm2(unsigned& r0, unsigned& r1, unsigned a) {
    asm volatile("ldmatrix.sync.aligned.m8n8.x2.shared.b16 {%0,%1},[%2];"
                 : "=r"(r0), "=r"(r1) : "r"(a));
}
__device__ __forceinline__ void mma16816(float* d,
    unsigned a0, unsigned a1, unsigned a2, unsigned a3,
    unsigned b0, unsigned b1) {
    asm volatile(
        "mma.sync.aligned.m16n8k16.row.col.f32.bf16.bf16.f32 "
        "{%0,%1,%2,%3},{%4,%5,%6,%7},{%8,%9},{%0,%1,%2,%3};"
        : "+f"(d[0]), "+f"(d[1]), "+f"(d[2]), "+f"(d[3])
        : "r"(a0), "r"(a1), "r"(a2), "r"(a3), "r"(b0), "r"(b1));
}
__device__ __forceinline__ void bsplit(float v, __nv_bfloat16& h, __nv_bfloat16& l) {
    h = __float2bfloat16(v);
    l = __float2bfloat16(v - __bfloat162float(h));
}
__device__ __forceinline__ unsigned bpack(__nv_bfloat16 a, __nv_bfloat16 b) {
    __nv_bfloat162 t = __halves2bfloat162(a, b);
    return *reinterpret_cast<unsigned*>(&t);
}

// ---------------------------------------------------------------------------
// Kernel 0: M = W1^T W2
// ---------------------------------------------------------------------------
__global__ __launch_bounds__(128) void mat_kernel(
    const float* __restrict__ W1, const float* __restrict__ W2)
{
    const int gi = blockIdx.x * 128 + threadIdx.x;
    const int c = gi >> 6, cp = gi & 63;
    float a0 = 0.0f, a1 = 0.0f;
#pragma unroll 16
    for (int o = 0; o < 64; o += 2) {
        a0 = fmaf(__ldg(&W1[o * 64 + c]),       __ldg(&W2[o * 64 + cp]),       a0);
        a1 = fmaf(__ldg(&W1[(o + 1) * 64 + c]), __ldg(&W2[(o + 1) * 64 + cp]), a1);
    }
    g_M[c * 64 + cp] = a0 + a1;
}

// ---------------------------------------------------------------------------
// Kernel 1 (mma.sync): y = M x AND v = W3 x, bf16 hi/lo split (3 terms).
// ---------------------------------------------------------------------------
__global__ __launch_bounds__(256) void qkv_mma_kernel(
    const float* __restrict__ x, const float* __restrict__ W3)
{
    extern __shared__ __align__(16) char qsm[];
    const unsigned sbase = smem_u32(qsm);
    __nv_bfloat16* xhi = (__nv_bfloat16*)(qsm + XHI_OFF);
    __nv_bfloat16* xlo = (__nv_bfloat16*)(qsm + XLO_OFF);
    __nv_bfloat16* wmh = (__nv_bfloat16*)(qsm + WMH_OFF);
    __nv_bfloat16* wml = (__nv_bfloat16*)(qsm + WML_OFF);
    __nv_bfloat16* wwh = (__nv_bfloat16*)(qsm + WWH_OFF);
    __nv_bfloat16* wwl = (__nv_bfloat16*)(qsm + WWL_OFF);

    const int tid  = threadIdx.x;
    const int w    = tid >> 5;
    const int lane = tid & 31;
    const int b  = blockIdx.y;
    const int n0 = blockIdx.x * 128;

    for (int i = tid; i < 4096; i += 256) {
        const int o = i >> 6, c = i & 63;
        __nv_bfloat16 h, l;
        bsplit(g_M[i], h, l);
        wmh[o * 72 + c] = h; wml[o * 72 + c] = l;
        bsplit(W3[i], h, l);
        wwh[o * 72 + c] = h; wwl[o * 72 + c] = l;
    }
    const float* xb = x + (size_t)b * C_ * HW_ + n0;
    for (int i = tid; i < 2048; i += 256) {
        const int c = i >> 5, j4 = (i & 31) * 4;
        const float4 t = *(const float4*)(xb + (size_t)c * HW_ + j4);
        __nv_bfloat16 h0, l0, h1, l1, h2, l2, h3, l3;
        bsplit(t.x, h0, l0); bsplit(t.y, h1, l1);
        bsplit(t.z, h2, l2); bsplit(t.w, h3, l3);
        *(unsigned*)&xhi[c * 136 + j4]     = bpack(h0, h1);
        *(unsigned*)&xhi[c * 136 + j4 + 2] = bpack(h2, h3);
        *(unsigned*)&xlo[c * 136 + j4]     = bpack(l0, l1);
        *(unsigned*)&xlo[c * 136 + j4 + 2] = bpack(l2, l3);
    }
    __syncthreads();

    const unsigned a_row = ((lane >> 4) & 1) * 8 + (lane & 7);
    const unsigned a_pxb = (16 * w + ((lane >> 3) & 1) * 8) * 2;
    const unsigned b_row = (lane & 7);
    const unsigned b_kb  = ((lane >> 3) & 1) * 16;

    float accY[8][4], accV[8][4];
#pragma unroll
    for (int nt = 0; nt < 8; nt++)
#pragma unroll
        for (int r = 0; r < 4; r++) { accY[nt][r] = 0.0f; accV[nt][r] = 0.0f; }

#pragma unroll
    for (int ks = 0; ks < 4; ks++) {
        const unsigned arow = (16 * ks + a_row) * XROWB + a_pxb;
        unsigned ah0, ah1, ah2, ah3, al0, al1, al2, al3;
        ldsm4t(ah0, ah1, ah2, ah3, sbase + XHI_OFF + arow);
        ldsm4t(al0, al1, al2, al3, sbase + XLO_OFF + arow);
#pragma unroll
        for (int nt = 0; nt < 8; nt++) {
            const unsigned boff = (nt * 8 + b_row) * WROWB + 32 * ks + b_kb;
            unsigned bh0, bh1, bl0, bl1;
            ldsm2(bh0, bh1, sbase + WMH_OFF + boff);
            ldsm2(bl0, bl1, sbase + WML_OFF + boff);
            mma16816(accY[nt], ah0, ah1, ah2, ah3, bh0, bh1);
            mma16816(accY[nt], al0, al1, al2, al3, bh0, bh1);
            mma16816(accY[nt], ah0, ah1, ah2, ah3, bl0, bl1);
            ldsm2(bh0, bh1, sbase + WWH_OFF + boff);
            ldsm2(bl0, bl1, sbase + WWL_OFF + boff);
            mma16816(accV[nt], ah0, ah1, ah2, ah3, bh0, bh1);
            mma16816(accV[nt], al0, al1, al2, al3, bh0, bh1);
            mma16816(accV[nt], ah0, ah1, ah2, ah3, bl0, bl1);
        }
    }
    __syncthreads();

    float* sD = (float*)qsm;
    const int g  = lane >> 2;
    const int o2 = 2 * (lane & 3);
    float* yb = g_y + (size_t)b * O_ * HW_ + n0;
    float* vb = g_v + (size_t)b * O_ * HW_ + n0;

#pragma unroll
    for (int nt = 0; nt < 8; nt++) {
        const int o0 = nt * 8 + o2;
        sD[o0 * DSTR + 16 * w + g]           = accY[nt][0];
        sD[(o0 + 1) * DSTR + 16 * w + g]     = accY[nt][1];
        sD[o0 * DSTR + 16 * w + g + 8]       = accY[nt][2];
        sD[(o0 + 1) * DSTR + 16 * w + g + 8] = accY[nt][3];
    }
    __syncthreads();
    for (int i = tid; i < 2048; i += 256) {
        const int o = i >> 5, j4 = (i & 31) * 4;
        *(float4*)(yb + (size_t)o * HW_ + j4) = *(const float4*)(sD + o * DSTR + j4);
    }
    __syncthreads();
#pragma unroll
    for (int nt = 0; nt < 8; nt++) {
        const int o0 = nt * 8 + o2;
        sD[o0 * DSTR + 16 * w + g]           = accV[nt][0];
        sD[(o0 + 1) * DSTR + 16 * w + g]     = accV[nt][1];
        sD[o0 * DSTR + 16 * w + g + 8]       = accV[nt][2];
        sD[(o0 + 1) * DSTR + 16 * w + g + 8] = accV[nt][3];
    }
    __syncthreads();
    for (int i = tid; i < 2048; i += 256) {
        const int o = i >> 5, j4 = (i & 31) * 4;
        *(float4*)(vb + (size_t)o * HW_ + j4) = *(const float4*)(sD + o * DSTR + j4);
    }
}

// ---------------------------------------------------------------------------
// Fused attention: 16x16 tile, 512 thr = 128 px-PAIRS x 4 dh-groups (2,2,2,1).
// 2-px unit -> tap state 28 regs -> <=64 regs -> 2 blocks x 512 thr = 32 warps/SM.
// Windows: 4 LDS.64 per (cc,dh), conflict-free at HSTR=48.
// ---------------------------------------------------------------------------
template<int NDH, int DH0>
__device__ __forceinline__ void score_accum2(
    float s[][2], const float* sH, const float* sX, int pair, int py, int ci2)
{
#pragma unroll
    for (int cc = 0; cc < 8; cc++) {
        const float2 q2 = *(const float2*)&sX[cc * 256 + py * 16 + ci2];
        const float* rowb = sH + cc * CH_STRIDE + (py + DH0) * HSTR + ci2;
#pragma unroll
        for (int d = 0; d < NDH; d++) {
            const float* rp = rowb + d * HSTR;
            const float2 w0 = *(const float2*)(rp);
            const float2 w1 = *(const float2*)(rp + 2);
            const float2 w2 = *(const float2*)(rp + 4);
            const float2 w3 = *(const float2*)(rp + 6);
            float* sb = &s[d * 7][0];
            sb[0]  = fmaf(q2.x, w0.x, sb[0]);  sb[1]  = fmaf(q2.y, w0.y, sb[1]);
            sb[2]  = fmaf(q2.x, w0.y, sb[2]);  sb[3]  = fmaf(q2.y, w1.x, sb[3]);
            sb[4]  = fmaf(q2.x, w1.x, sb[4]);  sb[5]  = fmaf(q2.y, w1.y, sb[5]);
            sb[6]  = fmaf(q2.x, w1.y, sb[6]);  sb[7]  = fmaf(q2.y, w2.x, sb[7]);
            sb[8]  = fmaf(q2.x, w2.x, sb[8]);  sb[9]  = fmaf(q2.y, w2.y, sb[9]);
            sb[10] = fmaf(q2.x, w2.y, sb[10]); sb[11] = fmaf(q2.y, w3.x, sb[11]);
            sb[12] = fmaf(q2.x, w3.x, sb[12]); sb[13] = fmaf(q2.y, w3.y, sb[13]);
        }
    }
}

template<int NDH, int DH0>
__device__ __forceinline__ void weight_chunk2(
    const float wt[][2], const float* sH, float2* pbuf,
    int g, int pair, int py, int ci2)
{
#pragma unroll
    for (int o = 0; o < 8; o++) {
        float a0 = 0.f, a1 = 0.f;
        const float* rowb = sH + o * CH_STRIDE + (py + DH0) * HSTR + ci2;
#pragma unroll
        for (int d = 0; d < NDH; d++) {
            const float* rp = rowb + d * HSTR;
            const float2 w0 = *(const float2*)(rp);
            const float2 w1 = *(const float2*)(rp + 2);
            const float2 w2 = *(const float2*)(rp + 4);
            const float2 w3 = *(const float2*)(rp + 6);
            const float* wb = &wt[d * 7][0];
            a0 = fmaf(wb[0],  w0.x, a0);  a1 = fmaf(wb[1],  w0.y, a1);
            a0 = fmaf(wb[2],  w0.y, a0);  a1 = fmaf(wb[3],  w1.x, a1);
            a0 = fmaf(wb[4],  w1.x, a0);  a1 = fmaf(wb[5],  w1.y, a1);
            a0 = fmaf(wb[6],  w1.y, a0);  a1 = fmaf(wb[7],  w2.x, a1);
            a0 = fmaf(wb[8],  w2.x, a0);  a1 = fmaf(wb[9],  w2.y, a1);
            a0 = fmaf(wb[10], w2.y, a0);  a1 = fmaf(wb[11], w3.x, a1);
            a0 = fmaf(wb[12], w3.x, a0);  a1 = fmaf(wb[13], w3.y, a1);
        }
        pbuf[(g * 8 + o) * 128 + pair] = make_float2(a0, a1);
    }
}

__global__ __launch_bounds__(512, 2) void attn_kernel(
    const float* __restrict__ x, float* __restrict__ out)
{
    extern __shared__ __align__(16) float smem[];
    float2* pbuf = (float2*)(smem + PB_OFF);
    float2* xch  = (float2*)(smem + PB_OFF + 6144);   // 512 float2 = 1024 floats

    const int tx   = threadIdx.x;
    const int pair = tx & 127;
    const int g    = tx >> 7;
    const int py   = pair >> 3;
    const int ci2  = (pair & 7) * 2;
    const int b  = blockIdx.z;
    const int h0 = blockIdx.y * 16, w0 = blockIdx.x * 16;

    const float* yb  = g_y + (size_t)b * C_ * HW_;
    const float* vb  = g_v + (size_t)b * C_ * HW_;
    const float* xbb = x + (size_t)b * C_ * HW_ + h0 * W_ + w0;

    // ---- Halo fill descriptor: one cell per thread (484 cells, 512 thr) ----
    const int j1 = tx;
    const bool has1 = (j1 < 484);
    const int r1 = j1 / 22, cl1 = j1 - 22 * r1;
    const int hh1 = h0 + r1 - PAD_, ww1 = w0 + cl1 - PAD_;
    const bool v1 = has1 && (hh1 >= 0 && hh1 < H_) && (ww1 >= 0 && ww1 < W_);
    const int so1 = r1 * HSTR + cl1;
    const int gp1 = v1 ? (hh1 * W_ + ww1 - h0 * W_ - w0) : 0;
    // sX descriptor: one float4 per thread (512 items)
    const int i0cc = tx >> 6, i0r = tx & 63;
    const int sxg0 = i0cc * HW_ + (i0r >> 2) * W_ + (i0r & 3) * 4;
    const int sxs0 = i0cc * 256 + i0r * 4;

    // ---- Zero OOB halo cells once ----
    if (has1 && !v1) {
#pragma unroll
        for (int cc = 0; cc < 8; cc++) {
            smem[SH0_OFF + cc * CH_STRIDE + so1] = 0.0f;
            smem[SH1_OFF + cc * CH_STRIDE + so1] = 0.0f;
        }
    }

    const float* ybase = yb + h0 * W_ + w0;
    const float* vbase = vb + h0 * W_ + w0;
    auto prefetch = [&](int k) {
        const int ch0 = (k & 7) * 8;
        const float* src = ((k < 8) ? ybase : vbase) + (size_t)ch0 * HW_;
        float* sH = smem + ((k & 1) ? SH1_OFF : SH0_OFF);
        if (v1) {
#pragma unroll
            for (int cc = 0; cc < 8; cc++)
                cpa4(&sH[cc * CH_STRIDE + so1], src + (size_t)cc * HW_ + gp1);
        }
        if (k < 8) {
            float* sX = smem + ((k & 1) ? SX1_OFF : SX0_OFF);
            cpa16(&sX[sxs0], xbb + (size_t)ch0 * HW_ + sxg0);
        }
        cpa_commit();
    };

    prefetch(0);
    prefetch(1);

    const int NT = (g < 3) ? 14 : 7;

    float s[14][2];
#pragma unroll
    for (int r = 0; r < 14; r++) { s[r][0] = 0.0f; s[r][1] = 0.0f; }

    // ---------------- Phase A: scores ----------------
    for (int i = 0; i < 8; i++) {
        cpa_wait<1>();
        __syncthreads();
        const float* sH = smem + ((i & 1) ? SH1_OFF : SH0_OFF);
        const float* sX = smem + ((i & 1) ? SX1_OFF : SX0_OFF);
        if      (g == 0) score_accum2<2, 0>(s, sH, sX, pair, py, ci2);
        else if (g == 1) score_accum2<2, 2>(s, sH, sX, pair, py, ci2);
        else if (g == 2) score_accum2<2, 4>(s, sH, sX, pair, py, ci2);
        else             score_accum2<1, 6>(s, sH, sX, pair, py, ci2);
        __syncthreads();
        prefetch(i + 2);
    }

    // ---------------- Softmax (4-way cross-group via xch) ----------------
    float m0 = -1e30f, m1 = -1e30f;
    for (int r = 0; r < NT; r++) {
        m0 = fmaxf(m0, s[r][0]); m1 = fmaxf(m1, s[r][1]);
    }
    xch[tx] = make_float2(m0, m1);
    __syncthreads();
    {
        float2 mm = xch[pair];
        m0 = mm.x; m1 = mm.y;
#pragma unroll
        for (int gg = 1; gg < 4; gg++) {
            const float2 t = xch[gg * 128 + pair];
            m0 = fmaxf(m0, t.x); m1 = fmaxf(m1, t.y);
        }
    }
    __syncthreads();

    float p0 = 0.f, p1 = 0.f;
    for (int r = 0; r < NT; r++) {
        s[r][0] = __expf(s[r][0] - m0); p0 += s[r][0];
        s[r][1] = __expf(s[r][1] - m1); p1 += s[r][1];
    }
    xch[tx] = make_float2(p0, p1);
    __syncthreads();
    {
        float2 ss = xch[pair];
        p0 = ss.x; p1 = ss.y;
#pragma unroll
        for (int gg = 1; gg < 4; gg++) {
            const float2 t = xch[gg * 128 + pair];
            p0 += t.x; p1 += t.y;
        }
    }
    const float i0 = __frcp_rn(p0), i1 = __frcp_rn(p1);
    for (int r = 0; r < NT; r++) { s[r][0] *= i0; s[r][1] *= i1; }
    __syncthreads();   // xch dead before pbuf reuse

    // ---------------- Phase B: weighting ----------------
    float* outb = out + (size_t)b * O_ * HW_;
    for (int i = 8; i < 16; i++) {
        if (i == 15) cpa_wait<0>(); else cpa_wait<1>();
        __syncthreads();
        const float* sH = smem + ((i & 1) ? SH1_OFF : SH0_OFF);
        const int ch0 = (i & 7) * 8;
        if      (g == 0) weight_chunk2<2, 0>(s, sH, pbuf, g, pair, py, ci2);
        else if (g == 1) weight_chunk2<2, 2>(s, sH, pbuf, g, pair, py, ci2);
        else if (g == 2) weight_chunk2<2, 4>(s, sH, pbuf, g, pair, py, ci2);
        else             weight_chunk2<1, 6>(s, sH, pbuf, g, pair, py, ci2);
        __syncthreads();

#pragma unroll
        for (int it = tx; it < 1024; it += 512) {
            const int o  = it >> 7;
            const int pr = it & 127;
            const float2 t0 = pbuf[(0 * 8 + o) * 128 + pr];
            const float2 t1 = pbuf[(1 * 8 + o) * 128 + pr];
            const float2 t2 = pbuf[(2 * 8 + o) * 128 + pr];
            const float2 t3 = pbuf[(3 * 8 + o) * 128 + pr];
            const int pyq = pr >> 3, cq = (pr & 7) * 2;
            *(float2*)(outb + (size_t)(ch0 + o) * HW_ + (h0 + pyq) * W_ + w0 + cq) =
                make_float2(t0.x + t1.x + t2.x + t3.x,
                            t0.y + t1.y + t2.y + t3.y);
        }
        if (i + 2 < 16) prefetch(i + 2);
    }
}

// ---------------------------------------------------------------------------
extern "C" void kernel_launch(void* const* d_in, const int* in_sizes, int n_in,
                              void* d_out, int out_size)
{
    const float* x  = (const float*)d_in[0];
    const float* W1 = (const float*)d_in[1];
    const float* W2 = (const float*)d_in[2];
    const float* W3 = (const float*)d_in[3];
    float* out = (float*)d_out;
    (void)in_sizes; (void)n_in; (void)out_size;

    cudaFuncSetAttribute(attn_kernel,
                         cudaFuncAttributeMaxDynamicSharedMemorySize, ATTN_SMEM);
    cudaFuncSetAttribute(qkv_mma_kernel,
                         cudaFuncAttributeMaxDynamicSharedMemorySize, QKV_SMEM);

    mat_kernel<<<32, 128>>>(W1, W2);
    qkv_mma_kernel<<<dim3(HW_ / 128, B_), 256, QKV_SMEM>>>(x, W3);
    attn_kernel<<<dim3(W_ / 16, H_ / 16, B_), 512, ATTN_SMEM>>>(x, out);
}

// round 16
// speedup vs baseline: 1.0538x; 1.0538x over previous
#include <cuda_runtime.h>
#include <cuda_bf16.h>

#define B_   8
#define C_   64
#define O_   64
#define H_   128
#define W_   128
#define HW_  16384
#define PAD_ 3
#define R_   49
#define HSTR 48                 // halo row stride (floats)
#define CH_STRIDE (22 * HSTR)   // 1056 floats per halo channel
#define HALO_F (8 * CH_STRIDE)  // 8448 floats per halo buffer

// attn smem layout (floats): sH0 | sH1 | region(8192: sX0|sX1 / xch / pbuf)
#define SH0_OFF  0
#define SH1_OFF  HALO_F
#define PB_OFF   (2 * HALO_F)
#define SX0_OFF  PB_OFF
#define SX1_OFF  (PB_OFF + 2048)
#define ATTN_SMEM ((2 * HALO_F + 8192) * 4)   // 100352 B

// qkv mma smem (bytes)
#define XHI_OFF  0
#define XLO_OFF  17408
#define WMH_OFF  34816
#define WML_OFF  44032
#define WWH_OFF  53248
#define WWL_OFF  62464
#define QKV_SMEM 71680
#define XROWB    272
#define WROWB    144
#define DSTR     132

// Scratch (device globals)
__device__ float g_y[B_ * C_ * HW_];
__device__ float g_v[B_ * C_ * HW_];
__device__ float g_M[64 * 64];

// -------------------- cp.async helpers --------------------
__device__ __forceinline__ void cpa4(float* smem_dst, const float* gsrc) {
    unsigned sa = (unsigned)__cvta_generic_to_shared(smem_dst);
    asm volatile("cp.async.ca.shared.global [%0], [%1], 4;" :: "r"(sa), "l"(gsrc));
}
__device__ __forceinline__ void cpa16(float* smem_dst, const float* gsrc) {
    unsigned sa = (unsigned)__cvta_generic_to_shared(smem_dst);
    asm volatile("cp.async.cg.shared.global [%0], [%1], 16;" :: "r"(sa), "l"(gsrc));
}
__device__ __forceinline__ void cpa_commit() {
    asm volatile("cp.async.commit_group;" ::: "memory");
}
template<int N>
__device__ __forceinline__ void cpa_wait() {
    asm volatile("cp.async.wait_group %0;" :: "n"(N) : "memory");
}

// -------------------- mma / ldmatrix helpers --------------------
__device__ __forceinline__ unsigned smem_u32(const void* p) {
    unsigned a;
    asm("{ .reg .u64 t; cvta.to.shared.u64 t, %1; cvt.u32.u64 %0, t; }"
        : "=r"(a) : "l"(p));
    return a;
}
__device__ __forceinline__ void ldsm4t(unsigned& r0, unsigned& r1,
                                       unsigned& r2, unsigned& r3, unsigned a) {
    asm volatile("ldmatrix.sync.aligned.m8n8.x4.trans.shared.b16 {%0,%1,%2,%3},[%4];"
                 : "=r"(r0), "=r"(r1), "=r"(r2), "=r"(r3) : "r"(a));
}
__device__ __forceinline__ void ldsm2(unsigned& r0, unsigned& r1, unsigned a) {
    asm volatile("ldmatrix.sync.aligned.m8n8.x2.shared.b16 {%0,%1},[%2];"
                 : "=r"(r0), "=r"(r1) : "r"(a));
}
__device__ __forceinline__ void mma16816(float* d,
    unsigned a0, unsigned a1, unsigned a2, unsigned a3,
    unsigned b0, unsigned b1) {
    asm volatile(
        "mma.sync.aligned.m16n8k16.row.col.f32.bf16.bf16.f32 "
        "{%0,%1,%2,%3},{%4,%5,%6,%7},{%8,%9},{%0,%1,%2,%3};"
        : "+f"(d[0]), "+f"(d[1]), "+f"(d[2]), "+f"(d[3])
        : "r"(a0), "r"(a1), "r"(a2), "r"(a3), "r"(b0), "r"(b1));
}
__device__ __forceinline__ void bsplit(float v, __nv_bfloat16& h, __nv_bfloat16& l) {
    h = __float2bfloat16(v);
    l = __float2bfloat16(v - __bfloat162float(h));
}
__device__ __forceinline__ unsigned bpack(__nv_bfloat16 a, __nv_bfloat16 b) {
    __nv_bfloat162 t = __halves2bfloat162(a, b);
    return *reinterpret_cast<unsigned*>(&t);
}

// ---------------------------------------------------------------------------
// Kernel 0: M = W1^T W2
// ---------------------------------------------------------------------------
__global__ __launch_bounds__(128) void mat_kernel(
    const float* __restrict__ W1, const float* __restrict__ W2)
{
    const int gi = blockIdx.x * 128 + threadIdx.x;
    const int c = gi >> 6, cp = gi & 63;
    float a0 = 0.0f, a1 = 0.0f;
#pragma unroll 16
    for (int o = 0; o < 64; o += 2) {
        a0 = fmaf(__ldg(&W1[o * 64 + c]),       __ldg(&W2[o * 64 + cp]),       a0);
        a1 = fmaf(__ldg(&W1[(o + 1) * 64 + c]), __ldg(&W2[(o + 1) * 64 + cp]), a1);
    }
    g_M[c * 64 + cp] = a0 + a1;
}

// ---------------------------------------------------------------------------
// Kernel 1 (mma.sync): y = M x AND v = W3 x, bf16 hi/lo split (3 terms).
// ---------------------------------------------------------------------------
__global__ __launch_bounds__(256) void qkv_mma_kernel(
    const float* __restrict__ x, const float* __restrict__ W3)
{
    extern __shared__ __align__(16) char qsm[];
    const unsigned sbase = smem_u32(qsm);
    __nv_bfloat16* xhi = (__nv_bfloat16*)(qsm + XHI_OFF);
    __nv_bfloat16* xlo = (__nv_bfloat16*)(qsm + XLO_OFF);
    __nv_bfloat16* wmh = (__nv_bfloat16*)(qsm + WMH_OFF);
    __nv_bfloat16* wml = (__nv_bfloat16*)(qsm + WML_OFF);
    __nv_bfloat16* wwh = (__nv_bfloat16*)(qsm + WWH_OFF);
    __nv_bfloat16* wwl = (__nv_bfloat16*)(qsm + WWL_OFF);

    const int tid  = threadIdx.x;
    const int w    = tid >> 5;
    const int lane = tid & 31;
    const int b  = blockIdx.y;
    const int n0 = blockIdx.x * 128;

    for (int i = tid; i < 4096; i += 256) {
        const int o = i >> 6, c = i & 63;
        __nv_bfloat16 h, l;
        bsplit(g_M[i], h, l);
        wmh[o * 72 + c] = h; wml[o * 72 + c] = l;
        bsplit(W3[i], h, l);
        wwh[o * 72 + c] = h; wwl[o * 72 + c] = l;
    }
    const float* xb = x + (size_t)b * C_ * HW_ + n0;
    for (int i = tid; i < 2048; i += 256) {
        const int c = i >> 5, j4 = (i & 31) * 4;
        const float4 t = *(const float4*)(xb + (size_t)c * HW_ + j4);
        __nv_bfloat16 h0, l0, h1, l1, h2, l2, h3, l3;
        bsplit(t.x, h0, l0); bsplit(t.y, h1, l1);
        bsplit(t.z, h2, l2); bsplit(t.w, h3, l3);
        *(unsigned*)&xhi[c * 136 + j4]     = bpack(h0, h1);
        *(unsigned*)&xhi[c * 136 + j4 + 2] = bpack(h2, h3);
        *(unsigned*)&xlo[c * 136 + j4]     = bpack(l0, l1);
        *(unsigned*)&xlo[c * 136 + j4 + 2] = bpack(l2, l3);
    }
    __syncthreads();

    const unsigned a_row = ((lane >> 4) & 1) * 8 + (lane & 7);
    const unsigned a_pxb = (16 * w + ((lane >> 3) & 1) * 8) * 2;
    const unsigned b_row = (lane & 7);
    const unsigned b_kb  = ((lane >> 3) & 1) * 16;

    float accY[8][4], accV[8][4];
#pragma unroll
    for (int nt = 0; nt < 8; nt++)
#pragma unroll
        for (int r = 0; r < 4; r++) { accY[nt][r] = 0.0f; accV[nt][r] = 0.0f; }

#pragma unroll
    for (int ks = 0; ks < 4; ks++) {
        const unsigned arow = (16 * ks + a_row) * XROWB + a_pxb;
        unsigned ah0, ah1, ah2, ah3, al0, al1, al2, al3;
        ldsm4t(ah0, ah1, ah2, ah3, sbase + XHI_OFF + arow);
        ldsm4t(al0, al1, al2, al3, sbase + XLO_OFF + arow);
#pragma unroll
        for (int nt = 0; nt < 8; nt++) {
            const unsigned boff = (nt * 8 + b_row) * WROWB + 32 * ks + b_kb;
            unsigned bh0, bh1, bl0, bl1;
            ldsm2(bh0, bh1, sbase + WMH_OFF + boff);
            ldsm2(bl0, bl1, sbase + WML_OFF + boff);
            mma16816(accY[nt], ah0, ah1, ah2, ah3, bh0, bh1);
            mma16816(accY[nt], al0, al1, al2, al3, bh0, bh1);
            mma16816(accY[nt], ah0, ah1, ah2, ah3, bl0, bl1);
            ldsm2(bh0, bh1, sbase + WWH_OFF + boff);
            ldsm2(bl0, bl1, sbase + WWL_OFF + boff);
            mma16816(accV[nt], ah0, ah1, ah2, ah3, bh0, bh1);
            mma16816(accV[nt], al0, al1, al2, al3, bh0, bh1);
            mma16816(accV[nt], ah0, ah1, ah2, ah3, bl0, bl1);
        }
    }
    __syncthreads();

    float* sD = (float*)qsm;
    const int g  = lane >> 2;
    const int o2 = 2 * (lane & 3);
    float* yb = g_y + (size_t)b * O_ * HW_ + n0;
    float* vb = g_v + (size_t)b * O_ * HW_ + n0;

#pragma unroll
    for (int nt = 0; nt < 8; nt++) {
        const int o0 = nt * 8 + o2;
        sD[o0 * DSTR + 16 * w + g]           = accY[nt][0];
        sD[(o0 + 1) * DSTR + 16 * w + g]     = accY[nt][1];
        sD[o0 * DSTR + 16 * w + g + 8]       = accY[nt][2];
        sD[(o0 + 1) * DSTR + 16 * w + g + 8] = accY[nt][3];
    }
    __syncthreads();
    for (int i = tid; i < 2048; i += 256) {
        const int o = i >> 5, j4 = (i & 31) * 4;
        *(float4*)(yb + (size_t)o * HW_ + j4) = *(const float4*)(sD + o * DSTR + j4);
    }
    __syncthreads();
#pragma unroll
    for (int nt = 0; nt < 8; nt++) {
        const int o0 = nt * 8 + o2;
        sD[o0 * DSTR + 16 * w + g]           = accV[nt][0];
        sD[(o0 + 1) * DSTR + 16 * w + g]     = accV[nt][1];
        sD[o0 * DSTR + 16 * w + g + 8]       = accV[nt][2];
        sD[(o0 + 1) * DSTR + 16 * w + g + 8] = accV[nt][3];
    }
    __syncthreads();
    for (int i = tid; i < 2048; i += 256) {
        const int o = i >> 5, j4 = (i & 31) * 4;
        *(float4*)(vb + (size_t)o * HW_ + j4) = *(const float4*)(sD + o * DSTR + j4);
    }
}

// Load 12-float window as 3 aligned LDS.128.
__device__ __forceinline__ void load_win(float* win, const float* rp) {
    const float4 A = *(const float4*)(rp);
    const float4 Bv = *(const float4*)(rp + 4);
    const float4 Cv = *(const float4*)(rp + 8);
    win[0] = A.x;  win[1] = A.y;  win[2] = A.z;  win[3] = A.w;
    win[4] = Bv.x; win[5] = Bv.y; win[6] = Bv.z; win[7] = Bv.w;
    win[8] = Cv.x; win[9] = Cv.y; win[10] = Cv.z; win[11] = Cv.w;
}

// ---------------------------------------------------------------------------
// Fused attention (R12 compute core, row-granular cpa16 halo fill).
// Halo rows hold 24 floats = gmem cols [w0-4, w0+20); window index shift +1.
// 16x16 tile, 256 thr = 64 quads x 4 dh-groups (2,2,2,1).
// ---------------------------------------------------------------------------
template<int NDH, int DH0>
__device__ __forceinline__ void score_accum(
    float s[][4], const float* sH, const float* sX, int quad, int py, int qx4)
{
#pragma unroll
    for (int cc = 0; cc < 8; cc++) {
        const float4 q4 = *(const float4*)&sX[cc * 256 + 4 * quad];
        const float* rowb = sH + cc * CH_STRIDE + (py + DH0) * HSTR + qx4;
#pragma unroll
        for (int d = 0; d < NDH; d++) {
            float win[12];
            load_win(win, rowb + d * HSTR);
#pragma unroll
            for (int dw = 0; dw < 7; dw++) {
                s[d * 7 + dw][0] = fmaf(q4.x, win[dw + 1], s[d * 7 + dw][0]);
                s[d * 7 + dw][1] = fmaf(q4.y, win[dw + 2], s[d * 7 + dw][1]);
                s[d * 7 + dw][2] = fmaf(q4.z, win[dw + 3], s[d * 7 + dw][2]);
                s[d * 7 + dw][3] = fmaf(q4.w, win[dw + 4], s[d * 7 + dw][3]);
            }
        }
    }
}

template<int NDH, int DH0>
__device__ __forceinline__ void weight_chunk(
    const float wt[][4], const float* sH, float4* pbuf,
    int g, int quad, int py, int qx4)
{
#pragma unroll
    for (int o = 0; o < 8; o++) {
        float a0 = 0.f, a1 = 0.f, a2 = 0.f, a3 = 0.f;
        const float* rowb = sH + o * CH_STRIDE + (py + DH0) * HSTR + qx4;
#pragma unroll
        for (int d = 0; d < NDH; d++) {
            float win[12];
            load_win(win, rowb + d * HSTR);
#pragma unroll
            for (int dw = 0; dw < 7; dw++) {
                a0 = fmaf(wt[d * 7 + dw][0], win[dw + 1], a0);
                a1 = fmaf(wt[d * 7 + dw][1], win[dw + 2], a1);
                a2 = fmaf(wt[d * 7 + dw][2], win[dw + 3], a2);
                a3 = fmaf(wt[d * 7 + dw][3], win[dw + 4], a3);
            }
        }
        pbuf[(g * 8 + o) * 64 + quad] = make_float4(a0, a1, a2, a3);
    }
}

__global__ __launch_bounds__(256, 2) void attn_kernel(
    const float* __restrict__ x, float* __restrict__ out)
{
    extern __shared__ __align__(16) float smem[];
    float4* pbuf = (float4*)(smem + PB_OFF);
    float4* xch  = (float4*)(smem + PB_OFF);

    const int tx   = threadIdx.x;
    const int quad = tx & 63;
    const int g    = tx >> 6;
    const int py   = quad >> 2;
    const int qx4  = (quad & 3) * 4;
    const int b  = blockIdx.z;
    const int h0 = blockIdx.y * 16, w0 = blockIdx.x * 16;

    const float* yb  = g_y + (size_t)b * C_ * HW_;
    const float* vb  = g_v + (size_t)b * C_ * HW_;
    const float* xbb = x + (size_t)b * C_ * HW_ + h0 * W_ + w0;

    const bool interior = (w0 >= 4) && (w0 + 20 <= W_);

    // ---- Interior row-fill descriptors: thread tx<176 owns (row=tx>>3, cc=tx&7)
    const int frow = tx >> 3;
    const int fcc  = tx & 7;
    const bool frow_ok = (tx < 176) &&
                         (h0 + frow - PAD_ >= 0) && (h0 + frow - PAD_ < H_);
    const int fi_s = fcc * CH_STRIDE + frow * HSTR;
    const int fi_g = fcc * HW_ + (frow - PAD_) * W_ - 4;

    // ---- Edge per-cell descriptors (hi = cl + 1 layout shift) ----
    const int j1 = tx;
    const int r1 = j1 / 22, cl1 = j1 - 22 * r1;
    const int hh1 = h0 + r1 - PAD_, ww1 = w0 + cl1 - PAD_;
    const bool v1 = (hh1 >= 0 && hh1 < H_ && ww1 >= 0 && ww1 < W_);
    const int so1 = r1 * HSTR + cl1 + 1;
    const int gp1 = v1 ? (hh1 * W_ + ww1 - h0 * W_ - w0) : 0;
    const int j2 = tx + 256;
    const bool has2 = (j2 < 484);
    const int r2 = j2 / 22, cl2 = j2 - 22 * r2;
    const int hh2 = h0 + r2 - PAD_, ww2 = w0 + cl2 - PAD_;
    const bool v2 = has2 && (hh2 >= 0 && hh2 < H_ && ww2 >= 0 && ww2 < W_);
    const int so2 = r2 * HSTR + cl2 + 1;
    const int gp2 = v2 ? (hh2 * W_ + ww2 - h0 * W_ - w0) : 0;
    // sX descriptors
    const int i0cc = tx >> 6,            i0r = tx & 63;
    const int i1cc = (tx + 256) >> 6,    i1r = (tx + 256) & 63;
    const int sxg0 = i0cc * HW_ + (i0r >> 2) * W_ + (i0r & 3) * 4;
    const int sxg1 = i1cc * HW_ + (i1r >> 2) * W_ + (i1r & 3) * 4;
    const int sxs0 = i0cc * 256 + i0r * 4;
    const int sxs1 = i1cc * 256 + i1r * 4;

    // ---- Zero all invalid halo cells once (rows 0..21, cols hi 0..23) ----
    for (int idx = tx; idx < 22 * 24; idx += 256) {
        const int r  = idx / 24, hi = idx - 24 * r;
        const int hh = h0 + r - PAD_, ww = w0 - 4 + hi;
        if (hh < 0 || hh >= H_ || ww < 0 || ww >= W_) {
            const int off = r * HSTR + hi;
#pragma unroll
            for (int cc = 0; cc < 8; cc++) {
                smem[SH0_OFF + cc * CH_STRIDE + off] = 0.0f;
                smem[SH1_OFF + cc * CH_STRIDE + off] = 0.0f;
            }
        }
    }

    const float* ybase = yb + h0 * W_ + w0;
    const float* vbase = vb + h0 * W_ + w0;
    auto prefetch = [&](int k) {
        const int ch0 = (k & 7) * 8;
        const float* src = ((k < 8) ? ybase : vbase) + (size_t)ch0 * HW_;
        float* sH = smem + ((k & 1) ? SH1_OFF : SH0_OFF);
        if (interior) {
            if (frow_ok) {
                float* d = &sH[fi_s];
                const float* gs = src + fi_g;
                cpa16(d,      gs);
                cpa16(d + 4,  gs + 4);
                cpa16(d + 8,  gs + 8);
                cpa16(d + 12, gs + 12);
                cpa16(d + 16, gs + 16);
                cpa16(d + 20, gs + 20);
            }
        } else {
            if (v1) {
#pragma unroll
                for (int cc = 0; cc < 8; cc++)
                    cpa4(&sH[cc * CH_STRIDE + so1], src + (size_t)cc * HW_ + gp1);
            }
            if (v2) {
#pragma unroll
                for (int cc = 0; cc < 8; cc++)
                    cpa4(&sH[cc * CH_STRIDE + so2], src + (size_t)cc * HW_ + gp2);
            }
        }
        if (k < 8) {
            float* sX = smem + ((k & 1) ? SX1_OFF : SX0_OFF);
            const float* xs = xbb + (size_t)ch0 * HW_;
            cpa16(&sX[sxs0], xs + sxg0);
            cpa16(&sX[sxs1], xs + sxg1);
        }
        cpa_commit();
    };

    prefetch(0);
    prefetch(1);

    const int NT = (g < 3) ? 14 : 7;

    float s[14][4];
#pragma unroll
    for (int r = 0; r < 14; r++)
#pragma unroll
        for (int p = 0; p < 4; p++) s[r][p] = 0.0f;

    // ---------------- Phase A: scores ----------------
    for (int i = 0; i < 8; i++) {
        cpa_wait<1>();
        __syncthreads();
        const float* sH = smem + ((i & 1) ? SH1_OFF : SH0_OFF);
        const float* sX = smem + ((i & 1) ? SX1_OFF : SX0_OFF);
        if      (g == 0) score_accum<2, 0>(s, sH, sX, quad, py, qx4);
        else if (g == 1) score_accum<2, 2>(s, sH, sX, quad, py, qx4);
        else if (g == 2) score_accum<2, 4>(s, sH, sX, quad, py, qx4);
        else             score_accum<1, 6>(s, sH, sX, quad, py, qx4);
        __syncthreads();
        prefetch(i + 2);
    }

    // ---------------- Softmax ----------------
    float4 pm = make_float4(-1e30f, -1e30f, -1e30f, -1e30f);
    for (int r = 0; r < NT; r++) {
        pm.x = fmaxf(pm.x, s[r][0]); pm.y = fmaxf(pm.y, s[r][1]);
        pm.z = fmaxf(pm.z, s[r][2]); pm.w = fmaxf(pm.w, s[r][3]);
    }
    xch[tx] = pm;
    __syncthreads();
    float4 m = xch[quad];
#pragma unroll
    for (int gg = 1; gg < 4; gg++) {
        const float4 t = xch[gg * 64 + quad];
        m.x = fmaxf(m.x, t.x); m.y = fmaxf(m.y, t.y);
        m.z = fmaxf(m.z, t.z); m.w = fmaxf(m.w, t.w);
    }
    __syncthreads();

    float4 ps = make_float4(0.f, 0.f, 0.f, 0.f);
    for (int r = 0; r < NT; r++) {
        s[r][0] = __expf(s[r][0] - m.x); ps.x += s[r][0];
        s[r][1] = __expf(s[r][1] - m.y); ps.y += s[r][1];
        s[r][2] = __expf(s[r][2] - m.z); ps.z += s[r][2];
        s[r][3] = __expf(s[r][3] - m.w); ps.w += s[r][3];
    }
    xch[tx] = ps;
    __syncthreads();
    float4 sum = xch[quad];
#pragma unroll
    for (int gg = 1; gg < 4; gg++) {
        const float4 t = xch[gg * 64 + quad];
        sum.x += t.x; sum.y += t.y; sum.z += t.z; sum.w += t.w;
    }
    const float4 inv = make_float4(__frcp_rn(sum.x), __frcp_rn(sum.y),
                                   __frcp_rn(sum.z), __frcp_rn(sum.w));
    for (int r = 0; r < NT; r++) {
        s[r][0] *= inv.x; s[r][1] *= inv.y; s[r][2] *= inv.z; s[r][3] *= inv.w;
    }
    __syncthreads();   // xch dead before pbuf reuse

    // ---------------- Phase B: weighting ----------------
    float* outb = out + (size_t)b * O_ * HW_;
    for (int i = 8; i < 16; i++) {
        if (i == 15) cpa_wait<0>(); else cpa_wait<1>();
        __syncthreads();
        const float* sH = smem + ((i & 1) ? SH1_OFF : SH0_OFF);
        const int ch0 = (i & 7) * 8;
        if      (g == 0) weight_chunk<2, 0>(s, sH, pbuf, g, quad, py, qx4);
        else if (g == 1) weight_chunk<2, 2>(s, sH, pbuf, g, quad, py, qx4);
        else if (g == 2) weight_chunk<2, 4>(s, sH, pbuf, g, quad, py, qx4);
        else             weight_chunk<1, 6>(s, sH, pbuf, g, quad, py, qx4);
        __syncthreads();

#pragma unroll
        for (int it = tx; it < 512; it += 256) {
            const int o  = it >> 6;
            const int qd = it & 63;
            const float4 t0 = pbuf[(0 * 8 + o) * 64 + qd];
            const float4 t1 = pbuf[(1 * 8 + o) * 64 + qd];
            const float4 t2 = pbuf[(2 * 8 + o) * 64 + qd];
            const float4 t3 = pbuf[(3 * 8 + o) * 64 + qd];
            const int pyq = qd >> 2, qxq = (qd & 3) * 4;
            *(float4*)(outb + (size_t)(ch0 + o) * HW_ + (h0 + pyq) * W_ + w0 + qxq) =
                make_float4(t0.x + t1.x + t2.x + t3.x,
                            t0.y + t1.y + t2.y + t3.y,
                            t0.z + t1.z + t2.z + t3.z,
                            t0.w + t1.w + t2.w + t3.w);
        }
        if (i + 2 < 16) prefetch(i + 2);
    }
}

// ---------------------------------------------------------------------------
extern "C" void kernel_launch(void* const* d_in, const int* in_sizes, int n_in,
                              void* d_out, int out_size)
{
    const float* x  = (const float*)d_in[0];
    const float* W1 = (const float*)d_in[1];
    const float* W2 = (const float*)d_in[2];
    const float* W3 = (const float*)d_in[3];
    float* out = (float*)d_out;
    (void)in_sizes; (void)n_in; (void)out_size;

    cudaFuncSetAttribute(attn_kernel,
                         cudaFuncAttributeMaxDynamicSharedMemorySize, ATTN_SMEM);
    cudaFuncSetAttribute(qkv_mma_kernel,
                         cudaFuncAttributeMaxDynamicSharedMemorySize, QKV_SMEM);

    mat_kernel<<<32, 128>>>(W1, W2);
    qkv_mma_kernel<<<dim3(HW_ / 128, B_), 256, QKV_SMEM>>>(x, W3);
    attn_kernel<<<dim3(W_ / 16, H_ / 16, B_), 256, ATTN_SMEM>>>(x, out);
}

// round 17
// speedup vs baseline: 1.0690x; 1.0144x over previous
#include <cuda_runtime.h>
#include <cuda_bf16.h>

#define B_   8
#define C_   64
#define O_   64
#define H_   128
#define W_   128
#define HW_  16384
#define PAD_ 3
#define R_   49
#define HSTR 48                 // halo row stride (floats)
#define CH_STRIDE (22 * HSTR)   // 1056 floats per halo channel
#define HALO_F (8 * CH_STRIDE)  // 8448 floats per halo buffer

// attn smem layout (floats): sH0 | sH1 | region(8192: sX0|sX1 / xch / pbuf)
#define SH0_OFF  0
#define SH1_OFF  HALO_F
#define PB_OFF   (2 * HALO_F)
#define SX0_OFF  PB_OFF
#define SX1_OFF  (PB_OFF + 2048)
#define ATTN_SMEM ((2 * HALO_F + 8192) * 4)   // 100352 B

// qkv split-kernel smem (bytes): xhi | xlo | wh | wl
#define XHI_OFF  0
#define XLO_OFF  17408
#define WH_OFF   34816
#define WL_OFF   44032
#define QKV_SMEM 53248
#define XROWB    272
#define WROWB    144
#define DSTR     132

// Scratch (device globals)
__device__ float g_y[B_ * C_ * HW_];
__device__ float g_v[B_ * C_ * HW_];
__device__ float g_M[64 * 64];

// -------------------- cp.async helpers --------------------
__device__ __forceinline__ void cpa4(float* smem_dst, const float* gsrc) {
    unsigned sa = (unsigned)__cvta_generic_to_shared(smem_dst);
    asm volatile("cp.async.ca.shared.global [%0], [%1], 4;" :: "r"(sa), "l"(gsrc));
}
__device__ __forceinline__ void cpa16(float* smem_dst, const float* gsrc) {
    unsigned sa = (unsigned)__cvta_generic_to_shared(smem_dst);
    asm volatile("cp.async.cg.shared.global [%0], [%1], 16;" :: "r"(sa), "l"(gsrc));
}
__device__ __forceinline__ void cpa_commit() {
    asm volatile("cp.async.commit_group;" ::: "memory");
}
template<int N>
__device__ __forceinline__ void cpa_wait() {
    asm volatile("cp.async.wait_group %0;" :: "n"(N) : "memory");
}

// -------------------- mma / ldmatrix helpers --------------------
__device__ __forceinline__ unsigned smem_u32(const void* p) {
    unsigned a;
    asm("{ .reg .u64 t; cvta.to.shared.u64 t, %1; cvt.u32.u64 %0, t; }"
        : "=r"(a) : "l"(p));
    return a;
}
__device__ __forceinline__ void ldsm4t(unsigned& r0, unsigned& r1,
                                       unsigned& r2, unsigned& r3, unsigned a) {
    asm volatile("ldmatrix.sync.aligned.m8n8.x4.trans.shared.b16 {%0,%1,%2,%3},[%4];"
                 : "=r"(r0), "=r"(r1), "=r"(r2), "=r"(r3) : "r"(a));
}
__device__ __forceinline__ void ldsm2(unsigned& r0, unsigned& r1, unsigned a) {
    asm volatile("ldmatrix.sync.aligned.m8n8.x2.shared.b16 {%0,%1},[%2];"
                 : "=r"(r0), "=r"(r1) : "r"(a));
}
__device__ __forceinline__ void mma16816(float* d,
    unsigned a0, unsigned a1, unsigned a2, unsigned a3,
    unsigned b0, unsigned b1) {
    asm volatile(
        "mma.sync.aligned.m16n8k16.row.col.f32.bf16.bf16.f32 "
        "{%0,%1,%2,%3},{%4,%5,%6,%7},{%8,%9},{%0,%1,%2,%3};"
        : "+f"(d[0]), "+f"(d[1]), "+f"(d[2]), "+f"(d[3])
        : "r"(a0), "r"(a1), "r"(a2), "r"(a3), "r"(b0), "r"(b1));
}
__device__ __forceinline__ void bsplit(float v, __nv_bfloat16& h, __nv_bfloat16& l) {
    h = __float2bfloat16(v);
    l = __float2bfloat16(v - __bfloat162float(h));
}
__device__ __forceinline__ unsigned bpack(__nv_bfloat16 a, __nv_bfloat16 b) {
    __nv_bfloat162 t = __halves2bfloat162(a, b);
    return *reinterpret_cast<unsigned*>(&t);
}

// ---------------------------------------------------------------------------
// Kernel 0: M = W1^T W2
// ---------------------------------------------------------------------------
__global__ __launch_bounds__(128) void mat_kernel(
    const float* __restrict__ W1, const float* __restrict__ W2)
{
    const int gi = blockIdx.x * 128 + threadIdx.x;
    const int c = gi >> 6, cp = gi & 63;
    float a0 = 0.0f, a1 = 0.0f;
#pragma unroll 16
    for (int o = 0; o < 64; o += 2) {
        a0 = fmaf(__ldg(&W1[o * 64 + c]),       __ldg(&W2[o * 64 + cp]),       a0);
        a1 = fmaf(__ldg(&W1[(o + 1) * 64 + c]), __ldg(&W2[(o + 1) * 64 + cp]), a1);
    }
    g_M[c * 64 + cp] = a0 + a1;
}

// ---------------------------------------------------------------------------
// Kernel 1 (mma.sync, split): z=0: y = M x;  z=1: v = W3 x.
// bf16 hi/lo (3 terms). 53 KB smem -> 3 blocks/SM (24 warps).
// ---------------------------------------------------------------------------
__global__ __launch_bounds__(256, 3) void qkv_split_kernel(
    const float* __restrict__ x, const float* __restrict__ W3)
{
    extern __shared__ __align__(16) char qsm[];
    const unsigned sbase = smem_u32(qsm);
    __nv_bfloat16* xhi = (__nv_bfloat16*)(qsm + XHI_OFF);
    __nv_bfloat16* xlo = (__nv_bfloat16*)(qsm + XLO_OFF);
    __nv_bfloat16* wh  = (__nv_bfloat16*)(qsm + WH_OFF);
    __nv_bfloat16* wl  = (__nv_bfloat16*)(qsm + WL_OFF);

    const int tid  = threadIdx.x;
    const int w    = tid >> 5;
    const int lane = tid & 31;
    const int b  = blockIdx.y;
    const int z  = blockIdx.z;
    const int n0 = blockIdx.x * 128;

    const float* Wm = (z == 0) ? g_M : W3;
    float* outp     = (z == 0) ? g_y : g_v;

    for (int i = tid; i < 4096; i += 256) {
        const int o = i >> 6, c = i & 63;
        __nv_bfloat16 h, l;
        bsplit(Wm[i], h, l);
        wh[o * 72 + c] = h; wl[o * 72 + c] = l;
    }
    const float* xb = x + (size_t)b * C_ * HW_ + n0;
    for (int i = tid; i < 2048; i += 256) {
        const int c = i >> 5, j4 = (i & 31) * 4;
        const float4 t = *(const float4*)(xb + (size_t)c * HW_ + j4);
        __nv_bfloat16 h0, l0, h1, l1, h2, l2, h3, l3;
        bsplit(t.x, h0, l0); bsplit(t.y, h1, l1);
        bsplit(t.z, h2, l2); bsplit(t.w, h3, l3);
        *(unsigned*)&xhi[c * 136 + j4]     = bpack(h0, h1);
        *(unsigned*)&xhi[c * 136 + j4 + 2] = bpack(h2, h3);
        *(unsigned*)&xlo[c * 136 + j4]     = bpack(l0, l1);
        *(unsigned*)&xlo[c * 136 + j4 + 2] = bpack(l2, l3);
    }
    __syncthreads();

    const unsigned a_row = ((lane >> 4) & 1) * 8 + (lane & 7);
    const unsigned a_pxb = (16 * w + ((lane >> 3) & 1) * 8) * 2;
    const unsigned b_row = (lane & 7);
    const unsigned b_kb  = ((lane >> 3) & 1) * 16;

    float acc[8][4];
#pragma unroll
    for (int nt = 0; nt < 8; nt++)
#pragma unroll
        for (int r = 0; r < 4; r++) acc[nt][r] = 0.0f;

#pragma unroll
    for (int ks = 0; ks < 4; ks++) {
        const unsigned arow = (16 * ks + a_row) * XROWB + a_pxb;
        unsigned ah0, ah1, ah2, ah3, al0, al1, al2, al3;
        ldsm4t(ah0, ah1, ah2, ah3, sbase + XHI_OFF + arow);
        ldsm4t(al0, al1, al2, al3, sbase + XLO_OFF + arow);
#pragma unroll
        for (int nt = 0; nt < 8; nt++) {
            const unsigned boff = (nt * 8 + b_row) * WROWB + 32 * ks + b_kb;
            unsigned bh0, bh1, bl0, bl1;
            ldsm2(bh0, bh1, sbase + WH_OFF + boff);
            ldsm2(bl0, bl1, sbase + WL_OFF + boff);
            mma16816(acc[nt], ah0, ah1, ah2, ah3, bh0, bh1);
            mma16816(acc[nt], al0, al1, al2, al3, bh0, bh1);
            mma16816(acc[nt], ah0, ah1, ah2, ah3, bl0, bl1);
        }
    }
    __syncthreads();

    float* sD = (float*)qsm;   // 64 x DSTR floats (33.8 KB), x tiles dead
    const int g  = lane >> 2;
    const int o2 = 2 * (lane & 3);
    float* ob = outp + (size_t)b * O_ * HW_ + n0;

#pragma unroll
    for (int nt = 0; nt < 8; nt++) {
        const int o0 = nt * 8 + o2;
        sD[o0 * DSTR + 16 * w + g]           = acc[nt][0];
        sD[(o0 + 1) * DSTR + 16 * w + g]     = acc[nt][1];
        sD[o0 * DSTR + 16 * w + g + 8]       = acc[nt][2];
        sD[(o0 + 1) * DSTR + 16 * w + g + 8] = acc[nt][3];
    }
    __syncthreads();
    for (int i = tid; i < 2048; i += 256) {
        const int o = i >> 5, j4 = (i & 31) * 4;
        *(float4*)(ob + (size_t)o * HW_ + j4) = *(const float4*)(sD + o * DSTR + j4);
    }
}

// Load 12-float window as 3 aligned LDS.128.
__device__ __forceinline__ void load_win(float* win, const float* rp) {
    const float4 A = *(const float4*)(rp);
    const float4 Bv = *(const float4*)(rp + 4);
    const float4 Cv = *(const float4*)(rp + 8);
    win[0] = A.x;  win[1] = A.y;  win[2] = A.z;  win[3] = A.w;
    win[4] = Bv.x; win[5] = Bv.y; win[6] = Bv.z; win[7] = Bv.w;
    win[8] = Cv.x; win[9] = Cv.y; win[10] = Cv.z; win[11] = Cv.w;
}

// ---------------------------------------------------------------------------
// Fused attention (R16: R12 compute core + row-granular cpa16 halo fill).
// Halo rows hold 24 floats = gmem cols [w0-4, w0+20); window index shift +1.
// ---------------------------------------------------------------------------
template<int NDH, int DH0>
__device__ __forceinline__ void score_accum(
    float s[][4], const float* sH, const float* sX, int quad, int py, int qx4)
{
#pragma unroll
    for (int cc = 0; cc < 8; cc++) {
        const float4 q4 = *(const float4*)&sX[cc * 256 + 4 * quad];
        const float* rowb = sH + cc * CH_STRIDE + (py + DH0) * HSTR + qx4;
#pragma unroll
        for (int d = 0; d < NDH; d++) {
            float win[12];
            load_win(win, rowb + d * HSTR);
#pragma unroll
            for (int dw = 0; dw < 7; dw++) {
                s[d * 7 + dw][0] = fmaf(q4.x, win[dw + 1], s[d * 7 + dw][0]);
                s[d * 7 + dw][1] = fmaf(q4.y, win[dw + 2], s[d * 7 + dw][1]);
                s[d * 7 + dw][2] = fmaf(q4.z, win[dw + 3], s[d * 7 + dw][2]);
                s[d * 7 + dw][3] = fmaf(q4.w, win[dw + 4], s[d * 7 + dw][3]);
            }
        }
    }
}

template<int NDH, int DH0>
__device__ __forceinline__ void weight_chunk(
    const float wt[][4], const float* sH, float4* pbuf,
    int g, int quad, int py, int qx4)
{
#pragma unroll
    for (int o = 0; o < 8; o++) {
        float a0 = 0.f, a1 = 0.f, a2 = 0.f, a3 = 0.f;
        const float* rowb = sH + o * CH_STRIDE + (py + DH0) * HSTR + qx4;
#pragma unroll
        for (int d = 0; d < NDH; d++) {
            float win[12];
            load_win(win, rowb + d * HSTR);
#pragma unroll
            for (int dw = 0; dw < 7; dw++) {
                a0 = fmaf(wt[d * 7 + dw][0], win[dw + 1], a0);
                a1 = fmaf(wt[d * 7 + dw][1], win[dw + 2], a1);
                a2 = fmaf(wt[d * 7 + dw][2], win[dw + 3], a2);
                a3 = fmaf(wt[d * 7 + dw][3], win[dw + 4], a3);
            }
        }
        pbuf[(g * 8 + o) * 64 + quad] = make_float4(a0, a1, a2, a3);
    }
}

__global__ __launch_bounds__(256, 2) void attn_kernel(
    const float* __restrict__ x, float* __restrict__ out)
{
    extern __shared__ __align__(16) float smem[];
    float4* pbuf = (float4*)(smem + PB_OFF);
    float4* xch  = (float4*)(smem + PB_OFF);

    const int tx   = threadIdx.x;
    const int quad = tx & 63;
    const int g    = tx >> 6;
    const int py   = quad >> 2;
    const int qx4  = (quad & 3) * 4;
    const int b  = blockIdx.z;
    const int h0 = blockIdx.y * 16, w0 = blockIdx.x * 16;

    const float* yb  = g_y + (size_t)b * C_ * HW_;
    const float* vb  = g_v + (size_t)b * C_ * HW_;
    const float* xbb = x + (size_t)b * C_ * HW_ + h0 * W_ + w0;

    const bool interior = (w0 >= 4) && (w0 + 20 <= W_);

    const int frow = tx >> 3;
    const int fcc  = tx & 7;
    const bool frow_ok = (tx < 176) &&
                         (h0 + frow - PAD_ >= 0) && (h0 + frow - PAD_ < H_);
    const int fi_s = fcc * CH_STRIDE + frow * HSTR;
    const int fi_g = fcc * HW_ + (frow - PAD_) * W_ - 4;

    const int j1 = tx;
    const int r1 = j1 / 22, cl1 = j1 - 22 * r1;
    const int hh1 = h0 + r1 - PAD_, ww1 = w0 + cl1 - PAD_;
    const bool v1 = (hh1 >= 0 && hh1 < H_ && ww1 >= 0 && ww1 < W_);
    const int so1 = r1 * HSTR + cl1 + 1;
    const int gp1 = v1 ? (hh1 * W_ + ww1 - h0 * W_ - w0) : 0;
    const int j2 = tx + 256;
    const bool has2 = (j2 < 484);
    const int r2 = j2 / 22, cl2 = j2 - 22 * r2;
    const int hh2 = h0 + r2 - PAD_, ww2 = w0 + cl2 - PAD_;
    const bool v2 = has2 && (hh2 >= 0 && hh2 < H_ && ww2 >= 0 && ww2 < W_);
    const int so2 = r2 * HSTR + cl2 + 1;
    const int gp2 = v2 ? (hh2 * W_ + ww2 - h0 * W_ - w0) : 0;
    const int i0cc = tx >> 6,            i0r = tx & 63;
    const int i1cc = (tx + 256) >> 6,    i1r = (tx + 256) & 63;
    const int sxg0 = i0cc * HW_ + (i0r >> 2) * W_ + (i0r & 3) * 4;
    const int sxg1 = i1cc * HW_ + (i1r >> 2) * W_ + (i1r & 3) * 4;
    const int sxs0 = i0cc * 256 + i0r * 4;
    const int sxs1 = i1cc * 256 + i1r * 4;

    for (int idx = tx; idx < 22 * 24; idx += 256) {
        const int r  = idx / 24, hi = idx - 24 * r;
        const int hh = h0 + r - PAD_, ww = w0 - 4 + hi;
        if (hh < 0 || hh >= H_ || ww < 0 || ww >= W_) {
            const int off = r * HSTR + hi;
#pragma unroll
            for (int cc = 0; cc < 8; cc++) {
                smem[SH0_OFF + cc * CH_STRIDE + off] = 0.0f;
                smem[SH1_OFF + cc * CH_STRIDE + off] = 0.0f;
            }
        }
    }

    const float* ybase = yb + h0 * W_ + w0;
    const float* vbase = vb + h0 * W_ + w0;
    auto prefetch = [&](int k) {
        const int ch0 = (k & 7) * 8;
        const float* src = ((k < 8) ? ybase : vbase) + (size_t)ch0 * HW_;
        float* sH = smem + ((k & 1) ? SH1_OFF : SH0_OFF);
        if (interior) {
            if (frow_ok) {
                float* d = &sH[fi_s];
                const float* gs = src + fi_g;
                cpa16(d,      gs);
                cpa16(d + 4,  gs + 4);
                cpa16(d + 8,  gs + 8);
                cpa16(d + 12, gs + 12);
                cpa16(d + 16, gs + 16);
                cpa16(d + 20, gs + 20);
            }
        } else {
            if (v1) {
#pragma unroll
                for (int cc = 0; cc < 8; cc++)
                    cpa4(&sH[cc * CH_STRIDE + so1], src + (size_t)cc * HW_ + gp1);
            }
            if (v2) {
#pragma unroll
                for (int cc = 0; cc < 8; cc++)
                    cpa4(&sH[cc * CH_STRIDE + so2], src + (size_t)cc * HW_ + gp2);
            }
        }
        if (k < 8) {
            float* sX = smem + ((k & 1) ? SX1_OFF : SX0_OFF);
            const float* xs = xbb + (size_t)ch0 * HW_;
            cpa16(&sX[sxs0], xs + sxg0);
            cpa16(&sX[sxs1], xs + sxg1);
        }
        cpa_commit();
    };

    prefetch(0);
    prefetch(1);

    const int NT = (g < 3) ? 14 : 7;

    float s[14][4];
#pragma unroll
    for (int r = 0; r < 14; r++)
#pragma unroll
        for (int p = 0; p < 4; p++) s[r][p] = 0.0f;

    // ---------------- Phase A: scores ----------------
    for (int i = 0; i < 8; i++) {
        cpa_wait<1>();
        __syncthreads();
        const float* sH = smem + ((i & 1) ? SH1_OFF : SH0_OFF);
        const float* sX = smem + ((i & 1) ? SX1_OFF : SX0_OFF);
        if      (g == 0) score_accum<2, 0>(s, sH, sX, quad, py, qx4);
        else if (g == 1) score_accum<2, 2>(s, sH, sX, quad, py, qx4);
        else if (g == 2) score_accum<2, 4>(s, sH, sX, quad, py, qx4);
        else             score_accum<1, 6>(s, sH, sX, quad, py, qx4);
        __syncthreads();
        prefetch(i + 2);
    }

    // ---------------- Softmax ----------------
    float4 pm = make_float4(-1e30f, -1e30f, -1e30f, -1e30f);
    for (int r = 0; r < NT; r++) {
        pm.x = fmaxf(pm.x, s[r][0]); pm.y = fmaxf(pm.y, s[r][1]);
        pm.z = fmaxf(pm.z, s[r][2]); pm.w = fmaxf(pm.w, s[r][3]);
    }
    xch[tx] = pm;
    __syncthreads();
    float4 m = xch[quad];
#pragma unroll
    for (int gg = 1; gg < 4; gg++) {
        const float4 t = xch[gg * 64 + quad];
        m.x = fmaxf(m.x, t.x); m.y = fmaxf(m.y, t.y);
        m.z = fmaxf(m.z, t.z); m.w = fmaxf(m.w, t.w);
    }
    __syncthreads();

    float4 ps = make_float4(0.f, 0.f, 0.f, 0.f);
    for (int r = 0; r < NT; r++) {
        s[r][0] = __expf(s[r][0] - m.x); ps.x += s[r][0];
        s[r][1] = __expf(s[r][1] - m.y); ps.y += s[r][1];
        s[r][2] = __expf(s[r][2] - m.z); ps.z += s[r][2];
        s[r][3] = __expf(s[r][3] - m.w); ps.w += s[r][3];
    }
    xch[tx] = ps;
    __syncthreads();
    float4 sum = xch[quad];
#pragma unroll
    for (int gg = 1; gg < 4; gg++) {
        const float4 t = xch[gg * 64 + quad];
        sum.x += t.x; sum.y += t.y; sum.z += t.z; sum.w += t.w;
    }
    const float4 inv = make_float4(__frcp_rn(sum.x), __frcp_rn(sum.y),
                                   __frcp_rn(sum.z), __frcp_rn(sum.w));
    for (int r = 0; r < NT; r++) {
        s[r][0] *= inv.x; s[r][1] *= inv.y; s[r][2] *= inv.z; s[r][3] *= inv.w;
    }
    __syncthreads();

    // ---------------- Phase B: weighting ----------------
    float* outb = out + (size_t)b * O_ * HW_;
    for (int i = 8; i < 16; i++) {
        if (i == 15) cpa_wait<0>(); else cpa_wait<1>();
        __syncthreads();
        const float* sH = smem + ((i & 1) ? SH1_OFF : SH0_OFF);
        const int ch0 = (i & 7) * 8;
        if      (g == 0) weight_chunk<2, 0>(s, sH, pbuf, g, quad, py, qx4);
        else if (g == 1) weight_chunk<2, 2>(s, sH, pbuf, g, quad, py, qx4);
        else if (g == 2) weight_chunk<2, 4>(s, sH, pbuf, g, quad, py, qx4);
        else             weight_chunk<1, 6>(s, sH, pbuf, g, quad, py, qx4);
        __syncthreads();

#pragma unroll
        for (int it = tx; it < 512; it += 256) {
            const int o  = it >> 6;
            const int qd = it & 63;
            const float4 t0 = pbuf[(0 * 8 + o) * 64 + qd];
            const float4 t1 = pbuf[(1 * 8 + o) * 64 + qd];
            const float4 t2 = pbuf[(2 * 8 + o) * 64 + qd];
            const float4 t3 = pbuf[(3 * 8 + o) * 64 + qd];
            const int pyq = qd >> 2, qxq = (qd & 3) * 4;
            *(float4*)(outb + (size_t)(ch0 + o) * HW_ + (h0 + pyq) * W_ + w0 + qxq) =
                make_float4(t0.x + t1.x + t2.x + t3.x,
                            t0.y + t1.y + t2.y + t3.y,
                            t0.z + t1.z + t2.z + t3.z,
                            t0.w + t1.w + t2.w + t3.w);
        }
        if (i + 2 < 16) prefetch(i + 2);
    }
}

// ---------------------------------------------------------------------------
extern "C" void kernel_launch(void* const* d_in, const int* in_sizes, int n_in,
                              void* d_out, int out_size)
{
    const float* x  = (const float*)d_in[0];
    const float* W1 = (const float*)d_in[1];
    const float* W2 = (const float*)d_in[2];
    const float* W3 = (const float*)d_in[3];
    float* out = (float*)d_out;
    (void)in_sizes; (void)n_in; (void)out_size;

    cudaFuncSetAttribute(attn_kernel,
                         cudaFuncAttributeMaxDynamicSharedMemorySize, ATTN_SMEM);
    cudaFuncSetAttribute(qkv_split_kernel,
                         cudaFuncAttributeMaxDynamicSharedMemorySize, QKV_SMEM);

    mat_kernel<<<32, 128>>>(W1, W2);
    qkv_split_kernel<<<dim3(HW_ / 128, B_, 2), 256, QKV_SMEM>>>(x, W3);
    attn_kernel<<<dim3(W_ / 16, H_ / 16, B_), 256, ATTN_SMEM>>>(x, out);
}